// round 16
// baseline (speedup 1.0000x reference)
#include <cuda_runtime.h>
#include <cstdint>

#define ALPHA 26
#define TPB   544                        // 17 warps, ONE block per SM
#define WARPS (TPB / 32)                 // 17
#define CHUNK_TOK    64                  // tokens per warp-chunk (2 per lane)
#define CHUNK_FLOATS (CHUNK_TOK * ALPHA) // 1664
#define CHUNK_BYTES  (CHUNK_FLOATS * 4)  // 6656 (16B multiple)
#define SEQ   8192
#define GRID  148                        // 1 block per SM
#define TW    (GRID * WARPS)             // 2516 warp pipelines

__device__ __forceinline__ uint32_t smem_u32(const void* p) {
    return (uint32_t)__cvta_generic_to_shared(p);
}
__device__ __forceinline__ void mbar_init(uint32_t mbar, uint32_t cnt) {
    asm volatile("mbarrier.init.shared.b64 [%0], %1;" :: "r"(mbar), "r"(cnt) : "memory");
}
__device__ __forceinline__ void mbar_expect_tx(uint32_t mbar, uint32_t bytes) {
    asm volatile("mbarrier.arrive.expect_tx.shared.b64 _, [%0], %1;"
                 :: "r"(mbar), "r"(bytes) : "memory");
}
__device__ __forceinline__ void mbar_wait(uint32_t mbar, uint32_t parity) {
    asm volatile(
        "{\n\t.reg .pred P;\n\t"
        "WAIT_%=:\n\t"
        "mbarrier.try_wait.parity.acquire.cta.shared::cta.b64 P, [%0], %1, 0x989680;\n\t"
        "@P bra.uni DONE_%=;\n\t"
        "bra.uni WAIT_%=;\n\t"
        "DONE_%=:\n\t}"
        :: "r"(mbar), "r"(parity) : "memory");
}
__device__ __forceinline__ void bulk_load(uint32_t sdst, const void* gsrc,
                                          uint32_t bytes, uint32_t mbar) {
    asm volatile(
        "cp.async.bulk.shared::cta.global.mbarrier::complete_tx::bytes [%0], [%1], %2, [%3];"
        :: "r"(sdst), "l"(gsrc), "r"(bytes), "r"(mbar) : "memory");
}
__device__ __forceinline__ void bulk_store(void* gdst, uint32_t ssrc, uint32_t bytes) {
    asm volatile("cp.async.bulk.global.shared::cta.bulk_group [%0], [%1], %2;"
                 :: "l"(gdst), "r"(ssrc), "r"(bytes) : "memory");
}
__device__ __forceinline__ void bulk_commit()    { asm volatile("cp.async.bulk.commit_group;" ::: "memory"); }
__device__ __forceinline__ void bulk_wait_read() { asm volatile("cp.async.bulk.wait_group.read 0;" ::: "memory"); }
__device__ __forceinline__ void bulk_wait_all()  { asm volatile("cp.async.bulk.wait_group 0;" ::: "memory"); }
__device__ __forceinline__ void fence_async()    { asm volatile("fence.proxy.async.shared::cta;" ::: "memory"); }

// ======== compute helpers ========
#define PACK_DUP(dst, v)  asm("mov.b64 %0, {%1, %1};" : "=l"(dst) : "f"(v))
#define PACK2(dst, a, b)  asm("mov.b64 %0, {%1, %2};" : "=l"(dst) : "f"(a), "f"(b))
#define UNPACK2(a, b, s)  asm("mov.b64 {%0, %1}, %2;" : "=f"(a), "=f"(b) : "l"(s))
#define FMA2(acc, b, x)   asm("fma.rn.f32x2 %0, %1, %2, %0;" : "+l"(acc) : "l"(b), "l"(x))
#define MUL2(d, a, b)     asm("mul.rn.f32x2 %0, %1, %2;" : "=l"(d) : "l"(a), "l"(b))

// full row FMA: 7 uniform loads from row pointer, 13 FMA2s per token accumulator
__device__ __forceinline__ void row_fma2(const char* rowp,
                                         unsigned long long* acc0, unsigned long long xx0,
                                         unsigned long long* acc1, unsigned long long xx1) {
    #pragma unroll
    for (int cc = 0; cc < 6; ++cc) {
        float4 f = *(const float4*)(rowp + 16 * cc);
        unsigned long long b01, b23;
        PACK2(b01, f.x, f.y);
        PACK2(b23, f.z, f.w);
        FMA2(acc0[2*cc  ], b01, xx0);
        FMA2(acc0[2*cc+1], b23, xx0);
        FMA2(acc1[2*cc  ], b01, xx1);
        FMA2(acc1[2*cc+1], b23, xx1);
    }
    float2 f = *(const float2*)(rowp + 96);
    unsigned long long bb;
    PACK2(bb, f.x, f.y);
    FMA2(acc0[12], bb, xx0);
    FMA2(acc1[12], bb, xx1);
}

// softmax (no max-subtract; unit-norm rows, x~N(0,1), |logit| < ~7) + packed writeback
__device__ __forceinline__ void softmax_store(const unsigned long long* acc,
                                              unsigned long long* w) {
    float e[ALPHA];
    #pragma unroll
    for (int p = 0; p < 13; ++p) {
        float a, b;
        UNPACK2(a, b, acc[p]);
        e[2*p] = __expf(a); e[2*p+1] = __expf(b);
    }
    float t[13];
    #pragma unroll
    for (int p = 0; p < 13; ++p) t[p] = e[2*p] + e[2*p+1];
    float sa = (t[0] + t[1]) + (t[2] + t[3]);
    float sb = (t[4] + t[5]) + (t[6] + t[7]);
    float sc = (t[8] + t[9]) + (t[10] + t[11]);
    float sm = (sa + sb) + (sc + t[12]);
    float inv = __fdividef(1.0f, sm);
    unsigned long long iv;
    PACK_DUP(iv, inv);
    #pragma unroll
    for (int p = 0; p < 13; ++p) {
        unsigned long long pk, r;
        PACK2(pk, e[2*p], e[2*p+1]);
        MUL2(r, pk, iv);
        w[p] = r;
    }
}

__global__ __launch_bounds__(TPB, 1)
void rotor_kernel(const float* __restrict__ x,
                  const float* __restrict__ rotor,
                  float* __restrict__ out, int nChunks)
{
    extern __shared__ __align__(128) float s_dyn[];     // WARPS * 2 * CHUNK_FLOATS
    __shared__ __align__(16) float s_rn[ALPHA][ALPHA + 2]; // normalized rotor, padded rows
    __shared__ float s_inv[ALPHA];
    __shared__ __align__(8) unsigned long long s_mbar[WARPS * 2];

    const int tid  = threadIdx.x;
    const int wid  = tid >> 5;
    const int lane = tid & 31;

    // --- normalize rotor rows into smem (once per persistent block) ---
    if (tid < ALPHA) {
        float ss = 0.f;
        #pragma unroll
        for (int j = 0; j < ALPHA; ++j) {
            float v = rotor[tid * ALPHA + j];
            ss = fmaf(v, v, ss);
        }
        s_inv[tid] = rsqrtf(ss);
    }
    if (tid < WARPS * 2) mbar_init(smem_u32(&s_mbar[tid]), 1);
    __syncthreads();
    for (int e = tid; e < ALPHA * ALPHA; e += TPB) {
        int r = e / ALPHA;
        s_rn[r][e - r * ALPHA] = rotor[e] * s_inv[r];
    }
    __syncthreads();   // rn + mbarrier init visible to all warps

    // per-warp resources
    float* __restrict__ wbuf = s_dyn + wid * 2 * CHUNK_FLOATS;
    const uint32_t wb  = smem_u32(wbuf);
    const uint32_t mbA = smem_u32(&s_mbar[wid * 2 + 0]);
    const uint32_t mbB = smem_u32(&s_mbar[wid * 2 + 1]);
    const char* rn_base = (const char*)&s_rn[0][0];

    const int c0 = blockIdx.x * WARPS + wid;   // this warp's first chunk

    // --- prologue: prefetch first two chunks (lane 0 only) ---
    if (lane == 0) {
        if (c0 < nChunks) {
            mbar_expect_tx(mbA, CHUNK_BYTES);
            bulk_load(wb, x + (size_t)c0 * CHUNK_FLOATS, CHUNK_BYTES, mbA);
        }
        if (c0 + TW < nChunks) {
            mbar_expect_tx(mbB, CHUNK_BYTES);
            bulk_load(wb + CHUNK_BYTES, x + (size_t)(c0 + TW) * CHUNK_FLOATS,
                      CHUNK_BYTES, mbB);
        }
    }

    int k = 0;
    for (int c = c0; c < nChunks; c += TW, ++k) {
        const int b  = k & 1;
        const int ph = (k >> 1) & 1;
        mbar_wait(b ? mbB : mbA, ph);

        float* __restrict__ sb = wbuf + b * CHUNK_FLOATS;

        // --- two tokens per lane ---
        const int tok0 = c * CHUNK_TOK + lane;
        const int tok1 = tok0 + 32;
        const int shift0 = (tok0 & (SEQ - 1)) % ALPHA;
        const int shift1 = (tok1 & (SEQ - 1)) % ALPHA;
        const float* __restrict__ xr0 = sb + lane * ALPHA;
        const float* __restrict__ xr1 = sb + (lane + 32) * ALPHA;

        unsigned long long acc0[13], acc1[13];
        #pragma unroll
        for (int p = 0; p < 13; ++p) { acc0[p] = 0ull; acc1[p] = 0ull; }

        #pragma unroll
        for (int r = 0; r < ALPHA; ++r) {
            int i0 = r - shift0; i0 += (i0 >> 31) & ALPHA;
            int i1 = r - shift1; i1 += (i1 >> 31) & ALPHA;
            unsigned long long xx0, xx1;
            PACK_DUP(xx0, xr0[i0]);
            PACK_DUP(xx1, xr1[i1]);
            row_fma2(rn_base + r * 112, acc0, xx0, acc1, xx1);
        }

        softmax_store(acc0, (unsigned long long*)(sb + lane * ALPHA));
        softmax_store(acc1, (unsigned long long*)(sb + (lane + 32) * ALPHA));
        __syncwarp();                                // warp's STS all done

        if (lane == 0) {
            fence_async();                           // STS visible to async proxy
            bulk_store(out + (size_t)c * CHUNK_FLOATS, wb + b * CHUNK_BYTES, CHUNK_BYTES);
            bulk_commit();
            const int cn = c + 2 * TW;
            if (cn < nChunks) {
                bulk_wait_read();                    // this buffer's store reads drained
                mbar_expect_tx(b ? mbB : mbA, CHUNK_BYTES);
                bulk_load(wb + b * CHUNK_BYTES, x + (size_t)cn * CHUNK_FLOATS,
                          CHUNK_BYTES, b ? mbB : mbA);
            }
        }
        // lanes 1..31 run ahead to next chunk's mbar_wait (other buffer) — safe
    }

    if (lane == 0) bulk_wait_all();                  // gmem stores complete before exit
}

extern "C" void kernel_launch(void* const* d_in, const int* in_sizes, int n_in,
                              void* d_out, int out_size)
{
    const float* x     = (const float*)d_in[0];   // [128, 8192, 26] f32
    const float* rotor = (const float*)d_in[1];   // [26, 26] f32
    float* out         = (float*)d_out;

    const int total_tokens = out_size / ALPHA;    // 1,048,576
    const int nChunks = total_tokens / CHUNK_TOK; // 16384

    const int dyn_smem = WARPS * 2 * CHUNK_BYTES; // 226304 B (17 warps)
    cudaFuncSetAttribute(rotor_kernel,
                         cudaFuncAttributeMaxDynamicSharedMemorySize, dyn_smem);

    rotor_kernel<<<GRID, TPB, dyn_smem>>>(x, rotor, out, nChunks);
}

// round 17
// speedup vs baseline: 1.1941x; 1.1941x over previous
#include <cuda_runtime.h>
#include <cstdint>

#define ALPHA 26
#define TPB   256
#define WARPS (TPB / 32)                 // 8 warps per block
#define CHUNK_TOK    64                  // tokens per warp-chunk (2 per lane)
#define CHUNK_FLOATS (CHUNK_TOK * ALPHA) // 1664
#define CHUNK_BYTES  (CHUNK_FLOATS * 4)  // 6656 (16B multiple)
#define SEQ   8192
#define GRID  296                        // 2 blocks/SM * 148 SMs
#define TW    (GRID * WARPS)             // 2368 warp pipelines

__device__ __forceinline__ uint32_t smem_u32(const void* p) {
    return (uint32_t)__cvta_generic_to_shared(p);
}
__device__ __forceinline__ void mbar_init(uint32_t mbar, uint32_t cnt) {
    asm volatile("mbarrier.init.shared.b64 [%0], %1;" :: "r"(mbar), "r"(cnt) : "memory");
}
__device__ __forceinline__ void mbar_expect_tx(uint32_t mbar, uint32_t bytes) {
    asm volatile("mbarrier.arrive.expect_tx.shared.b64 _, [%0], %1;"
                 :: "r"(mbar), "r"(bytes) : "memory");
}
__device__ __forceinline__ void mbar_wait(uint32_t mbar, uint32_t parity) {
    asm volatile(
        "{\n\t.reg .pred P;\n\t"
        "WAIT_%=:\n\t"
        "mbarrier.try_wait.parity.acquire.cta.shared::cta.b64 P, [%0], %1, 0x989680;\n\t"
        "@P bra.uni DONE_%=;\n\t"
        "bra.uni WAIT_%=;\n\t"
        "DONE_%=:\n\t}"
        :: "r"(mbar), "r"(parity) : "memory");
}
__device__ __forceinline__ void bulk_load(uint32_t sdst, const void* gsrc,
                                          uint32_t bytes, uint32_t mbar) {
    asm volatile(
        "cp.async.bulk.shared::cta.global.mbarrier::complete_tx::bytes [%0], [%1], %2, [%3];"
        :: "r"(sdst), "l"(gsrc), "r"(bytes), "r"(mbar) : "memory");
}
__device__ __forceinline__ void bulk_store(void* gdst, uint32_t ssrc, uint32_t bytes) {
    asm volatile("cp.async.bulk.global.shared::cta.bulk_group [%0], [%1], %2;"
                 :: "l"(gdst), "r"(ssrc), "r"(bytes) : "memory");
}
__device__ __forceinline__ void bulk_commit()     { asm volatile("cp.async.bulk.commit_group;" ::: "memory"); }
// allow the NEWEST group (chunk k-1's store, other buffer) to stay in flight;
// only groups <= k-2 (same buffer) must have drained their smem reads.
__device__ __forceinline__ void bulk_wait_read1() { asm volatile("cp.async.bulk.wait_group.read 1;" ::: "memory"); }
__device__ __forceinline__ void bulk_wait_all()   { asm volatile("cp.async.bulk.wait_group 0;" ::: "memory"); }
__device__ __forceinline__ void fence_async()     { asm volatile("fence.proxy.async.shared::cta;" ::: "memory"); }

// ======== compute helpers ========
#define PACK_DUP(dst, v)  asm("mov.b64 %0, {%1, %1};" : "=l"(dst) : "f"(v))
#define PACK2(dst, a, b)  asm("mov.b64 %0, {%1, %2};" : "=l"(dst) : "f"(a), "f"(b))
#define UNPACK2(a, b, s)  asm("mov.b64 {%0, %1}, %2;" : "=f"(a), "=f"(b) : "l"(s))
#define FMA2(acc, b, x)   asm("fma.rn.f32x2 %0, %1, %2, %0;" : "+l"(acc) : "l"(b), "l"(x))
#define MUL2(d, a, b)     asm("mul.rn.f32x2 %0, %1, %2;" : "=l"(d) : "l"(a), "l"(b))

// full row FMA: 7 uniform loads from row pointer, 13 FMA2s per token accumulator
__device__ __forceinline__ void row_fma2(const char* rowp,
                                         unsigned long long* acc0, unsigned long long xx0,
                                         unsigned long long* acc1, unsigned long long xx1) {
    #pragma unroll
    for (int cc = 0; cc < 6; ++cc) {
        float4 f = *(const float4*)(rowp + 16 * cc);
        unsigned long long b01, b23;
        PACK2(b01, f.x, f.y);
        PACK2(b23, f.z, f.w);
        FMA2(acc0[2*cc  ], b01, xx0);
        FMA2(acc0[2*cc+1], b23, xx0);
        FMA2(acc1[2*cc  ], b01, xx1);
        FMA2(acc1[2*cc+1], b23, xx1);
    }
    float2 f = *(const float2*)(rowp + 96);
    unsigned long long bb;
    PACK2(bb, f.x, f.y);
    FMA2(acc0[12], bb, xx0);
    FMA2(acc1[12], bb, xx1);
}

// softmax (no max-subtract; unit-norm rows, x~N(0,1), |logit| < ~7) + packed writeback
__device__ __forceinline__ void softmax_store(const unsigned long long* acc,
                                              unsigned long long* w) {
    float e[ALPHA];
    #pragma unroll
    for (int p = 0; p < 13; ++p) {
        float a, b;
        UNPACK2(a, b, acc[p]);
        e[2*p] = __expf(a); e[2*p+1] = __expf(b);
    }
    float t[13];
    #pragma unroll
    for (int p = 0; p < 13; ++p) t[p] = e[2*p] + e[2*p+1];
    float sa = (t[0] + t[1]) + (t[2] + t[3]);
    float sb = (t[4] + t[5]) + (t[6] + t[7]);
    float sc = (t[8] + t[9]) + (t[10] + t[11]);
    float sm = (sa + sb) + (sc + t[12]);
    float inv = __fdividef(1.0f, sm);
    unsigned long long iv;
    PACK_DUP(iv, inv);
    #pragma unroll
    for (int p = 0; p < 13; ++p) {
        unsigned long long pk, r;
        PACK2(pk, e[2*p], e[2*p+1]);
        MUL2(r, pk, iv);
        w[p] = r;
    }
}

__global__ __launch_bounds__(TPB, 2)
void rotor_kernel(const float* __restrict__ x,
                  const float* __restrict__ rotor,
                  float* __restrict__ out, int nChunks)
{
    extern __shared__ __align__(128) float s_dyn[];     // WARPS * 2 * CHUNK_FLOATS
    __shared__ __align__(16) float s_rn[ALPHA][ALPHA + 2]; // normalized rotor, padded rows
    __shared__ float s_inv[ALPHA];
    __shared__ __align__(8) unsigned long long s_mbar[WARPS * 2];

    const int tid  = threadIdx.x;
    const int wid  = tid >> 5;
    const int lane = tid & 31;

    // --- normalize rotor rows into smem (once per persistent block) ---
    if (tid < ALPHA) {
        float ss = 0.f;
        #pragma unroll
        for (int j = 0; j < ALPHA; ++j) {
            float v = rotor[tid * ALPHA + j];
            ss = fmaf(v, v, ss);
        }
        s_inv[tid] = rsqrtf(ss);
    }
    if (tid < WARPS * 2) mbar_init(smem_u32(&s_mbar[tid]), 1);
    __syncthreads();
    for (int e = tid; e < ALPHA * ALPHA; e += TPB) {
        int r = e / ALPHA;
        s_rn[r][e - r * ALPHA] = rotor[e] * s_inv[r];
    }
    __syncthreads();   // rn + mbarrier init visible to all warps

    // per-warp resources
    float* __restrict__ wbuf = s_dyn + wid * 2 * CHUNK_FLOATS;
    const uint32_t wb  = smem_u32(wbuf);
    const uint32_t mbA = smem_u32(&s_mbar[wid * 2 + 0]);
    const uint32_t mbB = smem_u32(&s_mbar[wid * 2 + 1]);
    const char* rn_base = (const char*)&s_rn[0][0];

    const int c0 = blockIdx.x * WARPS + wid;   // this warp's first chunk

    // --- prologue: prefetch first two chunks (lane 0 only) ---
    if (lane == 0) {
        if (c0 < nChunks) {
            mbar_expect_tx(mbA, CHUNK_BYTES);
            bulk_load(wb, x + (size_t)c0 * CHUNK_FLOATS, CHUNK_BYTES, mbA);
        }
        if (c0 + TW < nChunks) {
            mbar_expect_tx(mbB, CHUNK_BYTES);
            bulk_load(wb + CHUNK_BYTES, x + (size_t)(c0 + TW) * CHUNK_FLOATS,
                      CHUNK_BYTES, mbB);
        }
    }

    int k = 0;
    for (int c = c0; c < nChunks; c += TW, ++k) {
        const int b  = k & 1;
        const int ph = (k >> 1) & 1;
        mbar_wait(b ? mbB : mbA, ph);

        float* __restrict__ sb = wbuf + b * CHUNK_FLOATS;

        // --- two tokens per lane ---
        const int tok0 = c * CHUNK_TOK + lane;
        const int tok1 = tok0 + 32;
        const int shift0 = (tok0 & (SEQ - 1)) % ALPHA;
        const int shift1 = (tok1 & (SEQ - 1)) % ALPHA;

        // base pointers for modular x access: q0 for r >= shift, q1 (=q0+26) for r < shift
        const float* q0a = sb + lane * ALPHA - shift0;
        const float* q1a = q0a + ALPHA;
        const float* q0b = sb + (lane + 32) * ALPHA - shift1;
        const float* q1b = q0b + ALPHA;

        unsigned long long acc0[13], acc1[13];
        #pragma unroll
        for (int p = 0; p < 13; ++p) { acc0[p] = 0ull; acc1[p] = 0ull; }

        #pragma unroll
        for (int r = 0; r < ALPHA; ++r) {
            // x[(r - shift) mod 26]: pointer select + compile-time offset r
            float xv0 = (r < shift0 ? q1a : q0a)[r];
            float xv1 = (r < shift1 ? q1b : q0b)[r];
            unsigned long long xx0, xx1;
            PACK_DUP(xx0, xv0);
            PACK_DUP(xx1, xv1);
            row_fma2(rn_base + r * 112, acc0, xx0, acc1, xx1);
        }

        softmax_store(acc0, (unsigned long long*)(sb + lane * ALPHA));
        softmax_store(acc1, (unsigned long long*)(sb + (lane + 32) * ALPHA));
        __syncwarp();                                // warp's STS all done

        if (lane == 0) {
            fence_async();                           // STS visible to async proxy
            bulk_store(out + (size_t)c * CHUNK_FLOATS, wb + b * CHUNK_BYTES, CHUNK_BYTES);
            bulk_commit();
            const int cn = c + 2 * TW;
            if (cn < nChunks) {
                bulk_wait_read1();                   // only same-buffer (k-2) store must drain
                mbar_expect_tx(b ? mbB : mbA, CHUNK_BYTES);
                bulk_load(wb + b * CHUNK_BYTES, x + (size_t)cn * CHUNK_FLOATS,
                          CHUNK_BYTES, b ? mbB : mbA);
            }
        }
        // lanes 1..31 run ahead to next chunk's mbar_wait (other buffer) — safe
    }

    if (lane == 0) bulk_wait_all();                  // gmem stores complete before exit
}

extern "C" void kernel_launch(void* const* d_in, const int* in_sizes, int n_in,
                              void* d_out, int out_size)
{
    const float* x     = (const float*)d_in[0];   // [128, 8192, 26] f32
    const float* rotor = (const float*)d_in[1];   // [26, 26] f32
    float* out         = (float*)d_out;

    const int total_tokens = out_size / ALPHA;    // 1,048,576
    const int nChunks = total_tokens / CHUNK_TOK; // 16384

    const int dyn_smem = WARPS * 2 * CHUNK_BYTES; // 106496 B
    cudaFuncSetAttribute(rotor_kernel,
                         cudaFuncAttributeMaxDynamicSharedMemorySize, dyn_smem);

    rotor_kernel<<<GRID, TPB, dyn_smem>>>(x, rotor, out, nChunks);
}